// round 15
// baseline (speedup 1.0000x reference)
#include <cuda_runtime.h>
#include <math.h>

#define DIM      128
#define N_EDGES  800000
#define N_NODES  100000
#define META     20000
#define AUTHOR   50000
#define BATCH    8192
#define PAIRS    4096
#define HID      640

typedef unsigned long long ull;

// ---------------- device scratch (no allocations allowed) ----------------
__device__ float g_s0[AUTHOR * DIM];
__device__ float g_s1[AUTHOR * DIM];
__device__ float g_t0[AUTHOR];
__device__ float g_t1[AUTHOR];
__device__ unsigned char g_flag[AUTHOR];
__device__ float g_th0[N_NODES];
__device__ float g_th1[N_NODES];
// k-major matrices: M[k*128 + d]  (coalesced weight loads / cp.async staging)
__device__ __align__(16) float g_W3T[DIM * DIM];
__device__ __align__(16) float g_W4T[DIM * DIM];
__device__ __align__(16) float g_M6[DIM * DIM];
__device__ __align__(16) float g_M9[DIM * DIM];
__device__ __align__(16) float g_M7[DIM * DIM];
__device__ __align__(16) float g_M10[DIM * DIM];
__device__ __align__(16) float g_M12[DIM * DIM];
__device__ float g_bf[DIM];
__device__ float g_h[BATCH * DIM];

// ---------------- packed f32x2 helpers ----------------
__device__ __forceinline__ ull pk(float lo, float hi) {
    ull r; asm("mov.b64 %0, {%1,%2};" : "=l"(r) : "f"(lo), "f"(hi)); return r;
}
__device__ __forceinline__ ull dup2(float v) { return pk(v, v); }
__device__ __forceinline__ ull ffma2(ull a, ull b, ull c) {
    ull r; asm("fma.rn.f32x2 %0, %1, %2, %3;" : "=l"(r) : "l"(a), "l"(b), "l"(c)); return r;
}
__device__ __forceinline__ float2 upk(ull v) {
    float2 f; asm("mov.b64 {%0,%1}, %2;" : "=f"(f.x), "=f"(f.y) : "l"(v)); return f;
}

// ---------------- fused setup kernel ----------------
#define ZB   196
#define FB   320
#define TB   128
#define BFB  128
#define OB   32
#define THBG 391                     // theta blocks per graph (391*256 >= 100000)
#define THB  (2 * THBG)
#define SETUP_BLOCKS (ZB + FB + TB + BFB + OB + THB)

__global__ void __launch_bounds__(256) k_setup(
        const float* __restrict__ W3, const float* __restrict__ hp0, const float* __restrict__ b3,
        const float* __restrict__ W4, const float* __restrict__ hp1, const float* __restrict__ b4,
        const float* __restrict__ Wc, const float* __restrict__ bc,
        const float* __restrict__ W6, const float* __restrict__ b6,
        const float* __restrict__ W9, const float* __restrict__ b9,
        const float* __restrict__ W7, const float* __restrict__ b7,
        const float* __restrict__ W10, const float* __restrict__ b10,
        const float* __restrict__ W12, const float* __restrict__ b12,
        const float* __restrict__ b2, float* __restrict__ out,
        const float* __restrict__ sem0, const float* __restrict__ sem1) {
    __shared__ float red[256];
    __shared__ float u_s[DIM];
    int bx = blockIdx.x, tid = threadIdx.x;

    if (bx < ZB) {                                   // ---- zero flags
        int i = bx * 256 + tid;
        if (i < AUTHOR) g_flag[i] = 0;
        return;
    }
    bx -= ZB;
    if (bx < FB) {                                   // ---- fused M matrices (k-major store)
        int m = bx / 64;
        const float* R; float* M; int seg;
        switch (m) {
            case 0:  R = W6;  M = g_M6;  seg = 0; break;
            case 1:  R = W9;  M = g_M9;  seg = 0; break;
            case 2:  R = W7;  M = g_M7;  seg = 1; break;
            case 3:  R = W10; M = g_M10; seg = 1; break;
            default: R = W12; M = g_M12; seg = 2; break;
        }
        int o = (bx % 64) * 256 + tid;
        int d = o >> 7, k = o & 127;
        const float* wrow = Wc + (size_t)d * 384 + seg * 128;
        float a = 0.f;
        #pragma unroll 8
        for (int j = 0; j < DIM; j++) a += wrow[j] * R[j * DIM + k];
        M[k * DIM + d] = a;
        return;
    }
    bx -= FB;
    if (bx < TB) {                                   // ---- transpose W3, W4 to k-major
        int m = bx / 64;
        const float* W = m ? W4 : W3;
        float* T = m ? g_W4T : g_W3T;
        int o = (bx % 64) * 256 + tid;
        int d = o >> 7, k = o & 127;
        T[k * DIM + d] = W[o];
        return;
    }
    bx -= TB;
    if (bx < BFB) {                                  // ---- fused bias
        int i = bx;
        const float* w = Wc + (size_t)i * 384;
        float a = 0.f;
        {
            int j = tid;
            float v = (j < 128) ? (b6[j] + b9[j]) : (b7[j - 128] + b10[j - 128]);
            a = w[j] * v;
            if (tid < 128) a += w[256 + tid] * b12[tid];
        }
        red[tid] = a;
        __syncthreads();
        for (int s = 128; s > 32; s >>= 1) {
            if (tid < s) red[tid] += red[tid + s];
            __syncthreads();
        }
        if (tid < 32) {
            float v = red[tid] + red[tid + 32];
            #pragma unroll
            for (int o = 16; o; o >>= 1) v += __shfl_xor_sync(0xffffffffu, v, o);
            if (tid == 0) g_bf[i] = v + bc[i];
        }
        return;
    }
    bx -= BFB;
    if (bx < OB) {                                   // ---- init out with b2
        int idx = bx * 256 + tid;
        out[idx] = b2[idx & 1];
        return;
    }
    bx -= OB;
    {                                                // ---- theta = sem.u + c per node
        int g = (bx >= THBG) ? 1 : 0;
        int blk = bx - g * THBG;
        const float* W   = g ? W4  : W3;
        const float* hp  = g ? hp1 : hp0;
        const float* bb  = g ? b4  : b3;
        const float* sem = g ? sem1 : sem0;
        float* th = g ? g_th1 : g_th0;

        if (tid < DIM) {
            float a = 0.f;
            #pragma unroll 8
            for (int dd = 0; dd < DIM; dd++) a += W[dd * DIM + tid] * hp[dd];
            u_s[tid] = a;
            red[tid] = bb[tid] * hp[tid];
        } else red[tid] = 0.f;
        __syncthreads();
        for (int s = 64; s >= 1; s >>= 1) {
            if (tid < s) red[tid] += red[tid + s];
            __syncthreads();
        }
        float cb = red[0];

        int warp = tid >> 5, lane = tid & 31;
        float4 uv = ((const float4*)u_s)[lane];
        int nbase = (blk * 8 + warp) * 32;
        #pragma unroll 4
        for (int j = 0; j < 32; j++) {
            int n = nbase + j;
            if (n >= N_NODES) break;
            float4 x = ((const float4*)(sem + (size_t)n * DIM))[lane];
            float p = x.x * uv.x + x.y * uv.y + x.z * uv.z + x.w * uv.w;
            #pragma unroll
            for (int o = 16; o; o >>= 1) p += __shfl_xor_sync(0xffffffffu, p, o);
            if (lane == 0) th[n] = p + cb;
        }
    }
}

// mark needed author rows; zero their accumulators
__global__ void k_mark(const int* __restrict__ data) {
    int tid = blockIdx.x * blockDim.x + threadIdx.x;
    int b = tid >> 7, d = tid & 127;
    int r = data[b];
    g_s0[(size_t)r * DIM + d] = 0.f;
    g_s1[(size_t)r * DIM + d] = 0.f;
    if (d == 0) { g_t0[r] = 0.f; g_t1[r] = 0.f; g_flag[r] = 1; }
}

// ---------------- edge kernel: filter + weighted scatter (both graphs) ----------------
__global__ void k_edges(const int* __restrict__ ei0, const float* __restrict__ iv0,
                        const float* __restrict__ sem0,
                        const int* __restrict__ ei1, const float* __restrict__ iv1,
                        const float* __restrict__ sem1) {
    int which = blockIdx.y;
    const int*   rows = which ? ei1 : ei0;
    const int*   cols = (which ? ei1 : ei0) + N_EDGES;
    const float* interval = which ? iv1 : iv0;
    const float* sem = which ? sem1 : sem0;
    const float* th = which ? g_th1 : g_th0;
    float* s = which ? g_s1 : g_s0;
    float* t = which ? g_t1 : g_t0;

    int lane = threadIdx.x & 31;
    int base = (blockIdx.x * (blockDim.x >> 5) + (threadIdx.x >> 5)) * 32;
    if (base >= N_EDGES) return;

    int e = base + lane;
    int r = -1; bool ok = false;
    if (e < N_EDGES) {
        int row = rows[e];
        r = row - META;
        ok = ((unsigned)r < (unsigned)AUTHOR) && g_flag[r];
    }
    unsigned m = __ballot_sync(0xffffffffu, ok);
    if (!m) return;

    while (m) {
        int src = __ffs(m) - 1; m &= (m - 1);
        int rr = __shfl_sync(0xffffffffu, r, src);
        int ee = base + src;
        int col = cols[ee];
        float iv = interval[ee];
        float w = __expf(iv * th[col]);
        float4 x = ((const float4*)(sem + (size_t)col * DIM))[lane];
        float* sp = s + (size_t)rr * DIM + lane * 4;
        asm volatile("red.global.add.v4.f32 [%0], {%1, %2, %3, %4};"
                     :: "l"(sp), "f"(w * x.x), "f"(w * x.y), "f"(w * x.z), "f"(w * x.w)
                     : "memory");
        if (lane == 0) atomicAdd(&t[rr], w);
    }
}

// ---------------- fused dense stage: smem-staged weights via cp.async ----------------
// 512 threads, BS=32 (4 slots x 8 samples), 4 packed accs; weights double-buffered
// in 8KB (16-k) chunks; chunk c+1 transfers during compute of chunk c.
#define BS     32
#define SPS    8
#define PITCH  12
#define SLOTSZ (DIM * PITCH)         // 1536 floats
#define WCHUNK 2048                  // 16 k * 128 d floats = 8KB
#define NCH    8

__device__ __forceinline__ void issue_chunk(float* dst, const float* src, int tid) {
    unsigned sa = (unsigned)__cvta_generic_to_shared(dst + tid * 4);
    asm volatile("cp.async.cg.shared.global [%0], [%1], 16;\n\t"
                 "cp.async.commit_group;"
                 :: "r"(sa), "l"(src + tid * 4) : "memory");
}
__device__ __forceinline__ void wait0() {
    asm volatile("cp.async.wait_group 0;" ::: "memory");
}

__device__ __forceinline__ void chunk_pass(ull acc[4], const float* wsb, int d,
                                           const float* mybuf, int kbase) {
    #pragma unroll
    for (int kk = 0; kk < 16; kk++) {
        ull wd = dup2(wsb[kk * DIM + d]);
        const ulonglong2* xp = (const ulonglong2*)(mybuf + (kbase + kk) * PITCH);
        ulonglong2 va = xp[0], vb = xp[1];
        acc[0] = ffma2(wd, va.x, acc[0]);
        acc[1] = ffma2(wd, va.y, acc[1]);
        acc[2] = ffma2(wd, vb.x, acc[2]);
        acc[3] = ffma2(wd, vb.y, acc[3]);
    }
}

#define RUN_CHUNKS(MATP, NEXTP, ACC)                                            \
    for (int c = 0; c < NCH; c++) {                                             \
        if (c > 0) { wait0(); __syncthreads(); }                                \
        if (c < NCH - 1) issue_chunk(ws + (pb ^ 1) * WCHUNK,                    \
                                     (MATP) + (c + 1) * WCHUNK, tid);           \
        else if (NEXTP) issue_chunk(ws + (pb ^ 1) * WCHUNK,                     \
                                    (const float*)(NEXTP), tid);                \
        chunk_pass(ACC, ws + pb * WCHUNK, d, mybuf, c * 16);                    \
        pb ^= 1;                                                                \
    }

#define FILL_GATHER(PTR)                                                        \
    for (int i = tid; i < BS * DIM; i += 512) {                                 \
        int spl = i >> 7, k = i & 127;                                          \
        buf[(spl >> 3) * SLOTSZ + k * PITCH + (spl & 7)] =                      \
            (PTR)[(size_t)rs[spl] * DIM + k];                                   \
    }
#define FILL_DIRECT(PTR)                                                        \
    for (int i = tid; i < BS * DIM; i += 512) {                                 \
        int spl = i >> 7, k = i & 127;                                          \
        buf[(spl >> 3) * SLOTSZ + k * PITCH + (spl & 7)] =                      \
            (PTR)[(size_t)(bb + spl) * DIM + k];                                \
    }
#define G_WRITE(ACC)                                                            \
    _Pragma("unroll")                                                           \
    for (int j = 0; j < 4; j++) {                                               \
        float2 gv = upk((ACC)[j]);                                              \
        *(ull*)(mybuf + d * PITCH + 2 * j) =                                    \
            pk(fmaxf(gv.x, 0.f), fmaxf(gv.y, 0.f));                             \
    }

__global__ void __launch_bounds__(512) k_both(
        const float* __restrict__ b3, const float* __restrict__ c0,
        const float* __restrict__ b4, const float* __restrict__ c1,
        const float* __restrict__ st, const int* __restrict__ data) {
    __shared__ __align__(16) float ws[2 * WCHUNK];    // 16 KB
    __shared__ __align__(16) float buf[4 * SLOTSZ];   // 24 KB
    __shared__ float ts0[BS], ts1[BS];
    __shared__ int   rs[BS];

    int tid = threadIdx.x;
    int slot = tid >> 7, d = tid & 127;
    int bb = blockIdx.x * BS;
    int pb = 0;

    if (tid < BS) {
        int r = data[bb + tid];
        rs[tid] = r;
        ts0[tid] = g_t0[r];
        ts1[tid] = g_t1[r];
    }
    __syncthreads();                      // rs visible for gather fill

    issue_chunk(ws, g_W3T, tid);          // prologue: W3T chunk0 in flight
    FILL_GATHER(g_s0);

    float* mybuf = buf + slot * SLOTSZ;
    int sb = slot * SPS;

    ull h2[4], acc[4];
    #pragma unroll
    for (int j = 0; j < 4; j++) h2[j] = pk(0.f, 0.f);

    // ===== pass 0: g = W3 @ x0 (+ t0*b3) =====
    wait0(); __syncthreads();
    {
        float bw = b3[d];
        #pragma unroll
        for (int j = 0; j < 4; j++)
            acc[j] = pk(ts0[sb + 2 * j] * bw, ts0[sb + 2 * j + 1] * bw);
    }
    RUN_CHUNKS(g_W3T, g_M6, acc);

    // ===== pass 1: h += M6 @ relu(g) =====
    wait0(); __syncthreads();
    G_WRITE(acc);
    __syncthreads();
    RUN_CHUNKS(g_M6, g_M9, h2);

    // ===== pass 2: h += M9 @ c0 =====
    wait0(); __syncthreads();
    FILL_DIRECT(c0);
    __syncthreads();
    RUN_CHUNKS(g_M9, g_W4T, h2);

    // ===== pass 3: g = W4 @ x1 (+ t1*b4) =====
    wait0(); __syncthreads();
    FILL_GATHER(g_s1);
    __syncthreads();
    {
        float bw = b4[d];
        #pragma unroll
        for (int j = 0; j < 4; j++)
            acc[j] = pk(ts1[sb + 2 * j] * bw, ts1[sb + 2 * j + 1] * bw);
    }
    RUN_CHUNKS(g_W4T, g_M7, acc);

    // ===== pass 4: h += M7 @ relu(g) =====
    wait0(); __syncthreads();
    G_WRITE(acc);
    __syncthreads();
    RUN_CHUNKS(g_M7, g_M10, h2);

    // ===== pass 5: h += M10 @ c1 =====
    wait0(); __syncthreads();
    FILL_DIRECT(c1);
    __syncthreads();
    RUN_CHUNKS(g_M10, g_M12, h2);

    // ===== pass 6: h += M12 @ st; relu + bias =====
    wait0(); __syncthreads();
    FILL_DIRECT(st);
    __syncthreads();
    RUN_CHUNKS(g_M12, (const float*)0, h2);

    float bfd = g_bf[d];
    #pragma unroll
    for (int j = 0; j < 4; j++) {
        float2 hv = upk(h2[j]);
        g_h[(size_t)(bb + sb + 2 * j) * DIM + d]     = fmaxf(hv.x + bfd, 0.f);
        g_h[(size_t)(bb + sb + 2 * j + 1) * DIM + d] = fmaxf(hv.y + bfd, 0.f);
    }
}

// ---------------- pair stage, split over z-quarters; atomic combine ----------------
#define DPITCH 66
#define HQ     (HID / 4)
__global__ void __launch_bounds__(256) k_pairs(
        const float* __restrict__ W1, const float* __restrict__ b1,
        const float* __restrict__ W2,
        float* __restrict__ out) {
    __shared__ __align__(16) float dT[DIM * DPITCH];
    __shared__ float w1c[8 * DIM];
    __shared__ ull red0[8][32];
    __shared__ ull red1[8][32];

    int tid = threadIdx.x;
    int p = tid & 31, zs = tid >> 5;
    int pbase = blockIdx.x * 64;
    int zbase = blockIdx.y * HQ;

    for (int e = tid; e < 8192; e += 256) {
        int pp = e >> 7, k = e & 127;
        float a  = g_h[(size_t)(pbase + pp) * DIM + k];
        float bq = g_h[(size_t)(pbase + pp + PAIRS) * DIM + k];
        dT[k * DPITCH + pp] = fabsf(a - bq);
    }
    __syncthreads();

    ull o0 = pk(0.f, 0.f), o1 = pk(0.f, 0.f);
    const ull* drow = (const ull*)dT;
    for (int zc = 0; zc < HQ / 8; zc++) {
        for (int e = tid; e < 1024; e += 256) {
            int zz = e >> 7, k = e & 127;
            w1c[zz * DIM + k] = W1[(size_t)(zbase + zc * 8 + zz) * DIM + k];
        }
        __syncthreads();
        ull acc = pk(0.f, 0.f);
        #pragma unroll 8
        for (int k = 0; k < DIM; k++)
            acc = ffma2(dup2(w1c[zs * DIM + k]), drow[k * (DPITCH / 2) + p], acc);
        int z = zbase + zc * 8 + zs;
        float bz = b1[z];
        float2 av = upk(acc);
        ull zv = pk(fmaxf(av.x + bz, 0.f), fmaxf(av.y + bz, 0.f));
        o0 = ffma2(dup2(W2[z]),       zv, o0);
        o1 = ffma2(dup2(W2[HID + z]), zv, o1);
        __syncthreads();
    }
    red0[zs][p] = o0; red1[zs][p] = o1;
    __syncthreads();
    if (zs == 0) {
        float a0 = 0.f, a1 = 0.f, c0 = 0.f, c1 = 0.f;
        #pragma unroll
        for (int j = 0; j < 8; j++) {
            float2 v0 = upk(red0[j][p]); a0 += v0.x; c0 += v0.y;
            float2 v1 = upk(red1[j][p]); a1 += v1.x; c1 += v1.y;
        }
        int q0 = pbase + 2 * p, q1 = q0 + 1;
        atomicAdd(&out[(size_t)q0 * 2 + 0], a0);
        atomicAdd(&out[(size_t)q0 * 2 + 1], a1);
        atomicAdd(&out[(size_t)q1 * 2 + 0], c0);
        atomicAdd(&out[(size_t)q1 * 2 + 1], c1);
    }
}

// ---------------- launch ----------------
extern "C" void kernel_launch(void* const* d_in, const int* in_sizes, int n_in,
                              void* d_out, int out_size) {
    const float* sem0 = (const float*)d_in[0];
    const float* iv0  = (const float*)d_in[1];
    const int*   ei0  = (const int*)  d_in[2];
    const float* sem1 = (const float*)d_in[3];
    const float* iv1  = (const float*)d_in[4];
    const int*   ei1  = (const int*)  d_in[5];
    const float* c0   = (const float*)d_in[6];
    const float* c1   = (const float*)d_in[7];
    const int*   data = (const int*)  d_in[8];
    const float* st   = (const float*)d_in[9];
    const float* W1  = (const float*)d_in[10]; const float* b1  = (const float*)d_in[11];
    const float* W2  = (const float*)d_in[12]; const float* b2  = (const float*)d_in[13];
    const float* W3  = (const float*)d_in[14]; const float* b3  = (const float*)d_in[15];
    const float* W4  = (const float*)d_in[16]; const float* b4  = (const float*)d_in[17];
    const float* W6  = (const float*)d_in[18]; const float* b6  = (const float*)d_in[19];
    const float* W7  = (const float*)d_in[20]; const float* b7  = (const float*)d_in[21];
    const float* W9  = (const float*)d_in[22]; const float* b9  = (const float*)d_in[23];
    const float* W10 = (const float*)d_in[24]; const float* b10 = (const float*)d_in[25];
    const float* W12 = (const float*)d_in[26]; const float* b12 = (const float*)d_in[27];
    const float* Wc  = (const float*)d_in[28]; const float* bc  = (const float*)d_in[29];
    const float* hp0 = (const float*)d_in[30]; const float* hp1 = (const float*)d_in[31];
    float* out = (float*)d_out;

    k_setup<<<SETUP_BLOCKS, 256>>>(W3, hp0, b3, W4, hp1, b4, Wc, bc,
                                   W6, b6, W9, b9, W7, b7, W10, b10, W12, b12,
                                   b2, out, sem0, sem1);
    k_mark<<<(BATCH * DIM) / 256, 256>>>(data);

    int eblocks = (N_EDGES / 32 + 7) / 8;
    k_edges<<<dim3(eblocks, 2), 256>>>(ei0, iv0, sem0, ei1, iv1, sem1);

    k_both<<<BATCH / BS, 512>>>(b3, c0, b4, c1, st, data);

    k_pairs<<<dim3(PAIRS / 64, 4), 256>>>(W1, b1, W2, out);
    (void)in_sizes; (void)n_in; (void)out_size;
}

// round 16
// speedup vs baseline: 1.3970x; 1.3970x over previous
#include <cuda_runtime.h>
#include <math.h>
#include <cooperative_groups.h>
#include <cooperative_groups/reduce.h>

namespace cg = cooperative_groups;

#define DIM      128
#define N_EDGES  800000
#define META     20000
#define AUTHOR   50000
#define BATCH    8192
#define PAIRS    4096
#define HID      640

typedef unsigned long long ull;

// ---------------- device scratch (no allocations allowed) ----------------
__device__ float g_s0[AUTHOR * DIM];
__device__ float g_s1[AUTHOR * DIM];
__device__ float g_t0[AUTHOR];
__device__ float g_t1[AUTHOR];
__device__ unsigned char g_flag[AUTHOR];
__device__ __align__(16) float g_u0[132];   // u[128] + c at [128]
__device__ __align__(16) float g_u1[132];
// k-major matrices: M[k*128 + d]
__device__ __align__(16) float g_W3T[DIM * DIM];
__device__ __align__(16) float g_W4T[DIM * DIM];
__device__ __align__(16) float g_M6[DIM * DIM];
__device__ __align__(16) float g_M9[DIM * DIM];
__device__ __align__(16) float g_M7[DIM * DIM];
__device__ __align__(16) float g_M10[DIM * DIM];
__device__ __align__(16) float g_M12[DIM * DIM];
__device__ float g_bf[DIM];
__device__ float g_h[BATCH * DIM];

// ---------------- packed f32x2 helpers ----------------
__device__ __forceinline__ ull pk(float lo, float hi) {
    ull r; asm("mov.b64 %0, {%1,%2};" : "=l"(r) : "f"(lo), "f"(hi)); return r;
}
__device__ __forceinline__ ull dup2(float v) { return pk(v, v); }
__device__ __forceinline__ ull ffma2(ull a, ull b, ull c) {
    ull r; asm("fma.rn.f32x2 %0, %1, %2, %3;" : "=l"(r) : "l"(a), "l"(b), "l"(c)); return r;
}
__device__ __forceinline__ float2 upk(ull v) {
    float2 f; asm("mov.b64 {%0,%1}, %2;" : "=f"(f.x), "=f"(f.y) : "l"(v)); return f;
}

// ---------------- fused setup kernel ----------------
#define ZB  196
#define UB  2
#define FB  320
#define TB  128
#define BFB 128
#define OB  32
#define SETUP_BLOCKS (ZB + UB + FB + TB + BFB + OB)

__global__ void __launch_bounds__(256) k_setup(
        const float* __restrict__ W3, const float* __restrict__ hp0, const float* __restrict__ b3,
        const float* __restrict__ W4, const float* __restrict__ hp1, const float* __restrict__ b4,
        const float* __restrict__ Wc, const float* __restrict__ bc,
        const float* __restrict__ W6, const float* __restrict__ b6,
        const float* __restrict__ W9, const float* __restrict__ b9,
        const float* __restrict__ W7, const float* __restrict__ b7,
        const float* __restrict__ W10, const float* __restrict__ b10,
        const float* __restrict__ W12, const float* __restrict__ b12,
        const float* __restrict__ b2, float* __restrict__ out) {
    __shared__ float red[256];
    int bx = blockIdx.x, tid = threadIdx.x;

    if (bx < ZB) {                                   // ---- zero flags
        int i = bx * 256 + tid;
        if (i < AUTHOR) g_flag[i] = 0;
        return;
    }
    bx -= ZB;
    if (bx < UB) {                                   // ---- u = W^T hp, c = b.hp
        const float* W  = bx ? W4  : W3;
        const float* hp = bx ? hp1 : hp0;
        const float* bb = bx ? b4  : b3;
        float* u = bx ? g_u1 : g_u0;
        int k = tid;
        if (k < DIM) {
            float a = 0.f;
            #pragma unroll 8
            for (int d = 0; d < DIM; d++) a += W[d * DIM + k] * hp[d];
            u[k] = a;
            red[k] = bb[k] * hp[k];
        }
        __syncthreads();
        if (k < DIM) {
            for (int s = 64; s; s >>= 1) {
                if (k < s) red[k] += red[k + s];
                __syncwarp(0xffffffffu);
                if (s > 32) __syncthreads();
            }
            if (k == 0) u[DIM] = red[0];
        }
        return;
    }
    bx -= UB;
    if (bx < FB) {                                   // ---- fused M matrices (k-major store)
        int m = bx / 64;
        const float* R; float* M; int seg;
        switch (m) {
            case 0:  R = W6;  M = g_M6;  seg = 0; break;
            case 1:  R = W9;  M = g_M9;  seg = 0; break;
            case 2:  R = W7;  M = g_M7;  seg = 1; break;
            case 3:  R = W10; M = g_M10; seg = 1; break;
            default: R = W12; M = g_M12; seg = 2; break;
        }
        int o = (bx % 64) * 256 + tid;
        int d = o >> 7, k = o & 127;
        const float* wrow = Wc + (size_t)d * 384 + seg * 128;
        float a = 0.f;
        #pragma unroll 8
        for (int j = 0; j < DIM; j++) a += wrow[j] * R[j * DIM + k];
        M[k * DIM + d] = a;
        return;
    }
    bx -= FB;
    if (bx < TB) {                                   // ---- transpose W3, W4 to k-major
        int m = bx / 64;
        const float* W = m ? W4 : W3;
        float* T = m ? g_W4T : g_W3T;
        int o = (bx % 64) * 256 + tid;
        int d = o >> 7, k = o & 127;
        T[k * DIM + d] = W[o];
        return;
    }
    bx -= TB;
    if (bx < BFB) {                                  // ---- fused bias
        int i = bx;
        const float* w = Wc + (size_t)i * 384;
        float a = 0.f;
        {
            int j = tid;
            float v = (j < 128) ? (b6[j] + b9[j]) : (b7[j - 128] + b10[j - 128]);
            a = w[j] * v;
            if (tid < 128) a += w[256 + tid] * b12[tid];
        }
        red[tid] = a;
        __syncthreads();
        for (int s = 128; s > 32; s >>= 1) {
            if (tid < s) red[tid] += red[tid + s];
            __syncthreads();
        }
        if (tid < 32) {
            float v = red[tid] + red[tid + 32];
            #pragma unroll
            for (int o = 16; o; o >>= 1) v += __shfl_xor_sync(0xffffffffu, v, o);
            if (tid == 0) g_bf[i] = v + bc[i];
        }
        return;
    }
    bx -= BFB;
    {                                                // ---- init out with b2
        int idx = bx * 256 + tid;
        out[idx] = b2[idx & 1];
    }
}

// mark needed author rows; zero their accumulators
__global__ void k_mark(const int* __restrict__ data) {
    int tid = blockIdx.x * blockDim.x + threadIdx.x;
    int b = tid >> 7, d = tid & 127;
    int r = data[b];
    g_s0[(size_t)r * DIM + d] = 0.f;
    g_s1[(size_t)r * DIM + d] = 0.f;
    if (d == 0) { g_t0[r] = 0.f; g_t1[r] = 0.f; g_flag[r] = 1; }
}

// ---------------- edge kernel: filter + weighted scatter (both graphs) ----------------
__global__ void k_edges(const int* __restrict__ ei0, const float* __restrict__ iv0,
                        const float* __restrict__ sem0,
                        const int* __restrict__ ei1, const float* __restrict__ iv1,
                        const float* __restrict__ sem1) {
    int which = blockIdx.y;
    const int*   rows = which ? ei1 : ei0;
    const int*   cols = (which ? ei1 : ei0) + N_EDGES;
    const float* interval = which ? iv1 : iv0;
    const float* sem = which ? sem1 : sem0;
    const float* u = which ? g_u1 : g_u0;
    float* s = which ? g_s1 : g_s0;
    float* t = which ? g_t1 : g_t0;

    cg::thread_block_tile<32> warp = cg::tiled_partition<32>(cg::this_thread_block());

    int lane = threadIdx.x & 31;
    int base = (blockIdx.x * (blockDim.x >> 5) + (threadIdx.x >> 5)) * 32;
    if (base >= N_EDGES) return;

    int e = base + lane;
    int r = -1; bool ok = false;
    if (e < N_EDGES) {
        int row = rows[e];
        r = row - META;
        ok = ((unsigned)r < (unsigned)AUTHOR) && g_flag[r];
    }
    unsigned m = __ballot_sync(0xffffffffu, ok);
    if (!m) return;

    float4 uv = ((const float4*)u)[lane];
    float c = u[DIM];
    while (m) {
        int src = __ffs(m) - 1; m &= (m - 1);
        int rr = __shfl_sync(0xffffffffu, r, src);
        int ee = base + src;
        int col = cols[ee];
        float iv = interval[ee];
        float4 x = ((const float4*)(sem + (size_t)col * DIM))[lane];
        float p = x.x * uv.x + x.y * uv.y + x.z * uv.z + x.w * uv.w;
        p = cg::reduce(warp, p, cg::plus<float>());    // REDUX.F32 on sm_100a+
        float w = __expf(iv * (p + c));
        float* sp = s + (size_t)rr * DIM + lane * 4;
        asm volatile("red.global.add.v4.f32 [%0], {%1, %2, %3, %4};"
                     :: "l"(sp), "f"(w * x.x), "f"(w * x.y), "f"(w * x.z), "f"(w * x.w)
                     : "memory");
        if (lane == 0) atomicAdd(&t[rr], w);
    }
}

// ---------------- fused dense stage: register-tiled TM8 x TN4 ----------------
// 256 threads, BS=64 samples/block, grid 128.
// sg = tid>>5 (8 sample groups of 8), dg = tid&31 (32 output groups of 4).
// Per k: 1 LDG.128 (4 weights) + 2 broadcast LDS.128 (8 samples) + 16 FFMA2.
#define BS     64
#define PITCH  84            // floats per k-row (64 data + 20 pad; 336B, 16B-aligned)

__device__ __forceinline__ void mat_pass4(ull acc[4][4], const float* __restrict__ Mt,
                                          int d0, const float* __restrict__ buf, int s0) {
    #pragma unroll 8
    for (int k = 0; k < DIM; k++) {
        float4 w = *(const float4*)(Mt + (size_t)k * DIM + d0);
        const ulonglong2* xp = (const ulonglong2*)(buf + k * PITCH + s0);
        ulonglong2 va = xp[0], vb = xp[1];
        ull wd;
        wd = dup2(w.x);
        acc[0][0] = ffma2(wd, va.x, acc[0][0]);
        acc[0][1] = ffma2(wd, va.y, acc[0][1]);
        acc[0][2] = ffma2(wd, vb.x, acc[0][2]);
        acc[0][3] = ffma2(wd, vb.y, acc[0][3]);
        wd = dup2(w.y);
        acc[1][0] = ffma2(wd, va.x, acc[1][0]);
        acc[1][1] = ffma2(wd, va.y, acc[1][1]);
        acc[1][2] = ffma2(wd, vb.x, acc[1][2]);
        acc[1][3] = ffma2(wd, vb.y, acc[1][3]);
        wd = dup2(w.z);
        acc[2][0] = ffma2(wd, va.x, acc[2][0]);
        acc[2][1] = ffma2(wd, va.y, acc[2][1]);
        acc[2][2] = ffma2(wd, vb.x, acc[2][2]);
        acc[2][3] = ffma2(wd, vb.y, acc[2][3]);
        wd = dup2(w.w);
        acc[3][0] = ffma2(wd, va.x, acc[3][0]);
        acc[3][1] = ffma2(wd, va.y, acc[3][1]);
        acc[3][2] = ffma2(wd, vb.x, acc[3][2]);
        acc[3][3] = ffma2(wd, vb.y, acc[3][3]);
    }
}

#define FILL_GATHER(PTR)                                                        \
    for (int i = tid; i < BS * DIM; i += 256) {                                 \
        int spl = i >> 7, k = i & 127;                                          \
        buf[k * PITCH + spl] = (PTR)[(size_t)rs[spl] * DIM + k];                \
    }
#define FILL_DIRECT(PTR)                                                        \
    for (int i = tid; i < BS * DIM; i += 256) {                                 \
        int spl = i >> 7, k = i & 127;                                          \
        buf[k * PITCH + spl] = (PTR)[(size_t)(bb + spl) * DIM + k];             \
    }

__global__ void __launch_bounds__(256) k_both(
        const float* __restrict__ b3, const float* __restrict__ c0,
        const float* __restrict__ b4, const float* __restrict__ c1,
        const float* __restrict__ st, const int* __restrict__ data) {
    __shared__ __align__(16) float buf[DIM * PITCH];   // 43008 B
    __shared__ float ts0[BS], ts1[BS];
    __shared__ int   rs[BS];

    int tid = threadIdx.x;
    int sg = tid >> 5, dg = tid & 31;
    int s0 = sg * 8, d0 = dg * 4;
    int bb = blockIdx.x * BS;

    if (tid < BS) {
        int r = data[bb + tid];
        rs[tid] = r;
        ts0[tid] = g_t0[r];
        ts1[tid] = g_t1[r];
    }
    __syncthreads();

    ull h2[4][4], acc[4][4];
    #pragma unroll
    for (int dd = 0; dd < 4; dd++)
        #pragma unroll
        for (int jj = 0; jj < 4; jj++) h2[dd][jj] = pk(0.f, 0.f);

    // ===== side 0: g = relu(W3 @ x0 + t0*b3) =====
    FILL_GATHER(g_s0);
    __syncthreads();
    {
        float4 bw = *(const float4*)(b3 + d0);
        #pragma unroll
        for (int jj = 0; jj < 4; jj++) {
            float tl = ts0[s0 + 2 * jj], th = ts0[s0 + 2 * jj + 1];
            acc[0][jj] = pk(tl * bw.x, th * bw.x);
            acc[1][jj] = pk(tl * bw.y, th * bw.y);
            acc[2][jj] = pk(tl * bw.z, th * bw.z);
            acc[3][jj] = pk(tl * bw.w, th * bw.w);
        }
    }
    mat_pass4(acc, g_W3T, d0, buf, s0);
    __syncthreads();
    #pragma unroll
    for (int dd = 0; dd < 4; dd++)
        #pragma unroll
        for (int jj = 0; jj < 4; jj++) {
            float2 gv = upk(acc[dd][jj]);
            *(ull*)(buf + (d0 + dd) * PITCH + s0 + 2 * jj) =
                pk(fmaxf(gv.x, 0.f), fmaxf(gv.y, 0.f));
        }
    __syncthreads();
    mat_pass4(h2, g_M6, d0, buf, s0);
    __syncthreads();
    FILL_DIRECT(c0);
    __syncthreads();
    mat_pass4(h2, g_M9, d0, buf, s0);
    __syncthreads();

    // ===== side 1 =====
    FILL_GATHER(g_s1);
    __syncthreads();
    {
        float4 bw = *(const float4*)(b4 + d0);
        #pragma unroll
        for (int jj = 0; jj < 4; jj++) {
            float tl = ts1[s0 + 2 * jj], th = ts1[s0 + 2 * jj + 1];
            acc[0][jj] = pk(tl * bw.x, th * bw.x);
            acc[1][jj] = pk(tl * bw.y, th * bw.y);
            acc[2][jj] = pk(tl * bw.z, th * bw.z);
            acc[3][jj] = pk(tl * bw.w, th * bw.w);
        }
    }
    mat_pass4(acc, g_W4T, d0, buf, s0);
    __syncthreads();
    #pragma unroll
    for (int dd = 0; dd < 4; dd++)
        #pragma unroll
        for (int jj = 0; jj < 4; jj++) {
            float2 gv = upk(acc[dd][jj]);
            *(ull*)(buf + (d0 + dd) * PITCH + s0 + 2 * jj) =
                pk(fmaxf(gv.x, 0.f), fmaxf(gv.y, 0.f));
        }
    __syncthreads();
    mat_pass4(h2, g_M7, d0, buf, s0);
    __syncthreads();
    FILL_DIRECT(c1);
    __syncthreads();
    mat_pass4(h2, g_M10, d0, buf, s0);
    __syncthreads();

    // ===== structure branch + relu, vectorized STG.128 =====
    FILL_DIRECT(st);
    __syncthreads();
    mat_pass4(h2, g_M12, d0, buf, s0);
    {
        float4 bfv = *(const float4*)(g_bf + d0);
        #pragma unroll
        for (int jj = 0; jj < 4; jj++) {
            float2 v0 = upk(h2[0][jj]), v1 = upk(h2[1][jj]);
            float2 v2 = upk(h2[2][jj]), v3 = upk(h2[3][jj]);
            float4 lo, hi;
            lo.x = fmaxf(v0.x + bfv.x, 0.f); lo.y = fmaxf(v1.x + bfv.y, 0.f);
            lo.z = fmaxf(v2.x + bfv.z, 0.f); lo.w = fmaxf(v3.x + bfv.w, 0.f);
            hi.x = fmaxf(v0.y + bfv.x, 0.f); hi.y = fmaxf(v1.y + bfv.y, 0.f);
            hi.z = fmaxf(v2.y + bfv.z, 0.f); hi.w = fmaxf(v3.y + bfv.w, 0.f);
            *(float4*)(g_h + (size_t)(bb + s0 + 2 * jj) * DIM + d0)     = lo;
            *(float4*)(g_h + (size_t)(bb + s0 + 2 * jj + 1) * DIM + d0) = hi;
        }
    }
}

// ---------------- pair stage, split over z-quarters; atomic combine ----------------
#define DPITCH 66
#define HQ     (HID / 4)
__global__ void __launch_bounds__(256) k_pairs(
        const float* __restrict__ W1, const float* __restrict__ b1,
        const float* __restrict__ W2,
        float* __restrict__ out) {
    __shared__ __align__(16) float dT[DIM * DPITCH];
    __shared__ float w1c[8 * DIM];
    __shared__ ull red0[8][32];
    __shared__ ull red1[8][32];

    int tid = threadIdx.x;
    int p = tid & 31, zs = tid >> 5;
    int pbase = blockIdx.x * 64;
    int zbase = blockIdx.y * HQ;

    for (int e = tid; e < 8192; e += 256) {
        int pp = e >> 7, k = e & 127;
        float a  = g_h[(size_t)(pbase + pp) * DIM + k];
        float bq = g_h[(size_t)(pbase + pp + PAIRS) * DIM + k];
        dT[k * DPITCH + pp] = fabsf(a - bq);
    }
    __syncthreads();

    ull o0 = pk(0.f, 0.f), o1 = pk(0.f, 0.f);
    const ull* drow = (const ull*)dT;
    for (int zc = 0; zc < HQ / 8; zc++) {
        for (int e = tid; e < 1024; e += 256) {
            int zz = e >> 7, k = e & 127;
            w1c[zz * DIM + k] = W1[(size_t)(zbase + zc * 8 + zz) * DIM + k];
        }
        __syncthreads();
        ull acc = pk(0.f, 0.f);
        #pragma unroll 8
        for (int k = 0; k < DIM; k++)
            acc = ffma2(dup2(w1c[zs * DIM + k]), drow[k * (DPITCH / 2) + p], acc);
        int z = zbase + zc * 8 + zs;
        float bz = b1[z];
        float2 av = upk(acc);
        ull zv = pk(fmaxf(av.x + bz, 0.f), fmaxf(av.y + bz, 0.f));
        o0 = ffma2(dup2(W2[z]),       zv, o0);
        o1 = ffma2(dup2(W2[HID + z]), zv, o1);
        __syncthreads();
    }
    red0[zs][p] = o0; red1[zs][p] = o1;
    __syncthreads();
    if (zs == 0) {
        float a0 = 0.f, a1 = 0.f, c0 = 0.f, c1 = 0.f;
        #pragma unroll
        for (int j = 0; j < 8; j++) {
            float2 v0 = upk(red0[j][p]); a0 += v0.x; c0 += v0.y;
            float2 v1 = upk(red1[j][p]); a1 += v1.x; c1 += v1.y;
        }
        int q0 = pbase + 2 * p, q1 = q0 + 1;
        atomicAdd(&out[(size_t)q0 * 2 + 0], a0);
        atomicAdd(&out[(size_t)q0 * 2 + 1], a1);
        atomicAdd(&out[(size_t)q1 * 2 + 0], c0);
        atomicAdd(&out[(size_t)q1 * 2 + 1], c1);
    }
}

// ---------------- launch ----------------
extern "C" void kernel_launch(void* const* d_in, const int* in_sizes, int n_in,
                              void* d_out, int out_size) {
    const float* sem0 = (const float*)d_in[0];
    const float* iv0  = (const float*)d_in[1];
    const int*   ei0  = (const int*)  d_in[2];
    const float* sem1 = (const float*)d_in[3];
    const float* iv1  = (const float*)d_in[4];
    const int*   ei1  = (const int*)  d_in[5];
    const float* c0   = (const float*)d_in[6];
    const float* c1   = (const float*)d_in[7];
    const int*   data = (const int*)  d_in[8];
    const float* st   = (const float*)d_in[9];
    const float* W1  = (const float*)d_in[10]; const float* b1  = (const float*)d_in[11];
    const float* W2  = (const float*)d_in[12]; const float* b2  = (const float*)d_in[13];
    const float* W3  = (const float*)d_in[14]; const float* b3  = (const float*)d_in[15];
    const float* W4  = (const float*)d_in[16]; const float* b4  = (const float*)d_in[17];
    const float* W6  = (const float*)d_in[18]; const float* b6  = (const float*)d_in[19];
    const float* W7  = (const float*)d_in[20]; const float* b7  = (const float*)d_in[21];
    const float* W9  = (const float*)d_in[22]; const float* b9  = (const float*)d_in[23];
    const float* W10 = (const float*)d_in[24]; const float* b10 = (const float*)d_in[25];
    const float* W12 = (const float*)d_in[26]; const float* b12 = (const float*)d_in[27];
    const float* Wc  = (const float*)d_in[28]; const float* bc  = (const float*)d_in[29];
    const float* hp0 = (const float*)d_in[30]; const float* hp1 = (const float*)d_in[31];
    float* out = (float*)d_out;

    k_setup<<<SETUP_BLOCKS, 256>>>(W3, hp0, b3, W4, hp1, b4, Wc, bc,
                                   W6, b6, W9, b9, W7, b7, W10, b10, W12, b12,
                                   b2, out);
    k_mark<<<(BATCH * DIM) / 256, 256>>>(data);

    int eblocks = (N_EDGES / 32 + 7) / 8;
    k_edges<<<dim3(eblocks, 2), 256>>>(ei0, iv0, sem0, ei1, iv1, sem1);

    k_both<<<BATCH / BS, 256>>>(b3, c0, b4, c1, st, data);

    k_pairs<<<dim3(PAIRS / 64, 4), 256>>>(W1, b1, W2, out);
    (void)in_sizes; (void)n_in; (void)out_size;
}